// round 10
// baseline (speedup 1.0000x reference)
#include <cuda_runtime.h>
#include <cooperative_groups.h>
#include <stdint.h>

namespace cg = cooperative_groups;

#define NB   64
#define NC   768
#define NN   576
#define NG   3
#define GS   192
#define CSZ  16              // CTAs per cluster (one cluster = one (img,b) chunk)
#define CHC  (NC / CSZ)      // 48 channels per CTA
#define NT   512
#define NWARP 16

// dynamic smem layout (bytes):
//   [0, 110592)          data: 48 ch x 576 f32 (chunk slice)
//   [110592, 112896)     heatA: 576 f32
//   [112896, 115200)     heatB: 576 f32  (later reused: slab @+0, red @+1024, flags @+1536)
#define DATA_OFF   0
#define HEATA_OFF  (CHC * NN * 4)
#define HEATB_OFF  (HEATA_OFF + NN * 4)
#define SMEM_BYTES (HEATB_OFF + NN * 4)

__device__ float g_gsum[2 * NB * NG * NC];   // [img*NB + b][3*NC]
__device__ float g_partial[NB];
__device__ int   g_pair[NB];                 // self-resetting pair flags
__device__ int   g_counter;                  // self-resetting final counter

__device__ __forceinline__ float block_reduce16(float v, float* red) {
    const int lane = threadIdx.x & 31, w = threadIdx.x >> 5;
#pragma unroll
    for (int o = 16; o; o >>= 1) v += __shfl_down_sync(0xffffffffu, v, o);
    if (lane == 0) red[w] = v;
    __syncthreads();
    if (threadIdx.x < 16) {
        v = red[threadIdx.x];
#pragma unroll
        for (int o = 8; o; o >>= 1) v += __shfl_down_sync(0x0000ffffu, v, o);
        if (threadIdx.x == 0) red[0] = v;
    }
    __syncthreads();
    float rr = red[0];
    __syncthreads();
    return rr;
}

__global__ void __cluster_dims__(CSZ, 1, 1) __launch_bounds__(NT, 2)
fused16(const float* __restrict__ in0, const float* __restrict__ in1,
        float* __restrict__ out) {
    extern __shared__ char smem[];
    float*         data  = (float*)(smem + DATA_OFF);
    float*         heatA = (float*)(smem + HEATA_OFF);
    float*         heatB = (float*)(smem + HEATB_OFF);
    unsigned char* slab  = (unsigned char*)(smem + HEATB_OFF);        // reuse
    float*         red   = (float*)(smem + HEATB_OFF + 1024);         // reuse
    int*           flg   = (int*)(smem + HEATB_OFF + 1536);           // reuse

    cg::cluster_group cl = cg::this_cluster();
    const int r     = (int)cl.block_rank();      // 0..15
    const int chunk = blockIdx.x / CSZ;          // 0..127 = img*64 + b
    const int b     = chunk & (NB - 1);
    const int img   = chunk >> 6;
    const float* src = (img ? in1 : in0) + ((size_t)b * NC + (size_t)r * CHC) * NN;

    const int tid  = threadIdx.x;
    const int w    = tid >> 5;                   // 0..15
    const int lane = tid & 31;

    for (int n = tid; n < NN; n += NT) heatA[n] = 0.f;   // stride: 576 > 512!
    __syncthreads();

    // ---- Phase 1: stream own 48 channels once: LDG -> (heat partial regs, STS)
    float2 acc[9];
#pragma unroll
    for (int j = 0; j < 9; ++j) acc[j] = make_float2(0.f, 0.f);
#pragma unroll
    for (int k = 0; k < CHC / NWARP; ++k) {      // 3 channels per warp
        const int c = w + NWARP * k;
        const float2* row  = (const float2*)(src + (size_t)c * NN);
        float2*       drow = (float2*)(data + c * NN);
#pragma unroll
        for (int j = 0; j < 9; ++j) {
            float2 v = row[lane + 32 * j];
            drow[lane + 32 * j] = v;
            acc[j].x += v.x;
            acc[j].y += v.y;
        }
    }
#pragma unroll
    for (int j = 0; j < 9; ++j) {
        int n = 2 * (lane + 32 * j);
        atomicAdd(&heatA[n],     acc[j].x);
        atomicAdd(&heatA[n + 1], acc[j].y);
    }
    __syncthreads();
    cl.sync();                                   // all 16 partial heats ready

    // ---- Butterfly combine over DSMEM: 4 rounds, all ranks end bitwise-equal
    float* sbuf = heatA;
    float* dbuf = heatB;
#pragma unroll
    for (int d = 1; d < CSZ; d <<= 1) {
        const float* peer = cl.map_shared_rank(sbuf, r ^ d);
        for (int n = tid; n < NN; n += NT) dbuf[n] = sbuf[n] + peer[n];
        __syncthreads();
        cl.sync();
        float* t = sbuf; sbuf = dbuf; dbuf = t;
    }
    // after 4 rounds sbuf == heatA holds the full 768-channel heat; heatB free

    // ---- Rank + tercile label (identical on all ranks): warp w owns 36 n's
    {
        float kr[18];
#pragma unroll
        for (int j = 0; j < 18; ++j) kr[j] = heatA[lane + 32 * j];
#pragma unroll
        for (int i = 0; i < 36; ++i) {
            int n = 36 * w + i;
            float hn = heatA[n];
            unsigned cnt = 0;
#pragma unroll
            for (int j = 0; j < 18; ++j) {
                int m = lane + 32 * j;
                cnt += (kr[j] > hn) || (kr[j] == hn && m < n);
            }
            unsigned rk = __reduce_add_sync(0xffffffffu, cnt);
            if (lane == 0) slab[n] = (unsigned char)(rk / GS);
        }
    }
    __syncthreads();

    // ---- Per-lane label bitmasks (positions 2*(lane+32j), +1)
    unsigned bm0 = 0, bm1 = 0;
#pragma unroll
    for (int j = 0; j < 9; ++j) {
        int n = 2 * (lane + 32 * j);
        unsigned char l0 = slab[n], l1 = slab[n + 1];
        bm0 |= ((l0 == 0) ? 1u : 0u) << (2 * j);
        bm0 |= ((l1 == 0) ? 1u : 0u) << (2 * j + 1);
        bm1 |= ((l0 == 1) ? 1u : 0u) << (2 * j);
        bm1 |= ((l1 == 1) ? 1u : 0u) << (2 * j + 1);
    }

    // ---- Group sums from SMEM (no second DRAM pass)
    float* dst = g_gsum + (size_t)chunk * NG * NC;
#pragma unroll
    for (int k = 0; k < CHC / NWARP; ++k) {
        const int c = w + NWARP * k;
        const float2* row = (const float2*)(data + c * NN);
        float tot = 0.f, s0 = 0.f, s1 = 0.f;
#pragma unroll
        for (int j = 0; j < 9; ++j) {
            float2 v = row[lane + 32 * j];
            tot += v.x + v.y;
            if ((bm0 >> (2 * j)) & 1u)     s0 += v.x;
            if ((bm0 >> (2 * j + 1)) & 1u) s0 += v.y;
            if ((bm1 >> (2 * j)) & 1u)     s1 += v.x;
            if ((bm1 >> (2 * j + 1)) & 1u) s1 += v.y;
        }
#pragma unroll
        for (int o = 16; o; o >>= 1) {
            tot += __shfl_down_sync(0xffffffffu, tot, o);
            s0  += __shfl_down_sync(0xffffffffu, s0, o);
            s1  += __shfl_down_sync(0xffffffffu, s1, o);
        }
        if (lane == 0) {
            int cg_ = r * CHC + c;
            dst[cg_]          = s0;
            dst[NC + cg_]     = s1;
            dst[2 * NC + cg_] = tot - s0 - s1;   // 1/192 cancels in L2 norm
        }
    }
    __threadfence();
    __syncthreads();
    cl.sync();          // gsum writes of all 16 CTAs ordered; DSMEM safe to exit

    if (r != 0) return;

    // ---- Pairing epilogue (rank-0 CTA only): second arrival per b does SSD
    if (tid == 0) {
        int prev = atomicAdd(&g_pair[b], 1);
        if (prev == 1) { g_pair[b] = 0; *flg = 1; }   // self-reset for replay
        else           { *flg = 0; }
    }
    __syncthreads();
    if (!*flg) return;
    __threadfence();

    const float* v1 = g_gsum + (size_t)b * NG * NC;
    const float* v2 = g_gsum + (size_t)(NB + b) * NG * NC;

    float ss1 = 0.f, ss2 = 0.f;
    for (int i = tid; i < NG * NC; i += NT) {
        float a = v1[i], c = v2[i];
        ss1 = fmaf(a, a, ss1);
        ss2 = fmaf(c, c, ss2);
    }
    ss1 = block_reduce16(ss1, red);
    ss2 = block_reduce16(ss2, red);
    float i1 = 1.f / fmaxf(sqrtf(ss1), 1e-12f);
    float i2 = 1.f / fmaxf(sqrtf(ss2), 1e-12f);

    float acc2 = 0.f;
    for (int i = tid; i < NG * NC; i += NT) {
        float d = v1[i] * i1 - v2[i] * i2;
        acc2 = fmaf(d, d, acc2);
    }
    acc2 = block_reduce16(acc2, red);

    if (tid == 0) {
        g_partial[b] = acc2;
        __threadfence();
        int prev = atomicAdd(&g_counter, 1);
        if (prev == NB - 1) { g_counter = 0; *flg = 1; }
        else                { *flg = 0; }
    }
    __syncthreads();

    if (*flg && tid < 32) {
        float v = g_partial[tid] + g_partial[tid + 32];
#pragma unroll
        for (int o = 16; o; o >>= 1) v += __shfl_down_sync(0xffffffffu, v, o);
        if (tid == 0) out[0] = v * (1.f / (float)(NB * NG * NC));
    }
}

extern "C" void kernel_launch(void* const* d_in, const int* in_sizes, int n_in,
                              void* d_out, int out_size) {
    const float* in0 = (const float*)d_in[0];
    const float* in1 = (const float*)d_in[1];
    float* out = (float*)d_out;
    (void)in_sizes; (void)n_in; (void)out_size;

    cudaFuncSetAttribute(fused16, cudaFuncAttributeMaxDynamicSharedMemorySize, SMEM_BYTES);
    cudaFuncSetAttribute(fused16, cudaFuncAttributeNonPortableClusterSizeAllowed, 1);

    fused16<<<2 * NB * CSZ, NT, SMEM_BYTES>>>(in0, in1, out);
}

// round 11
// speedup vs baseline: 1.3944x; 1.3944x over previous
#include <cuda_runtime.h>
#include <cuda_bf16.h>
#include <cooperative_groups.h>
#include <stdint.h>

namespace cg = cooperative_groups;

#define NB   64
#define NC   768
#define NN   576
#define NG   3
#define GS   192
#define CSZ  8               // CTAs per cluster; cluster = one (img,b) chunk
#define CHC  (NC / CSZ)      // 96 channels per CTA
#define NT   1024
#define NWARP 32

// dynamic smem layout (bytes)
#define DATA_OFF   0                         // CHC*NN bf16 = 110592
#define BUF_OFF    110592                    // 8*NN f32 tree staging = 18432
#define HEATC_OFF  129024                    // NN f32 = 2304
#define SLAB_OFF   131328                    // NN bytes = 576
#define RED_OFF    131904                    // 32 f32
#define FLG_OFF    132032                    // int
#define SMEM_TOTAL 132096

__device__ float g_heatP[2 * NB * CSZ * NN];   // per-(chunk,rank) heat partials
__device__ float g_gsum [2 * NB * NG * NC];    // [chunk][g][c]
__device__ float g_partial[NB];
__device__ int   g_done[NB];                   // counts 16 CTAs per b (self-reset)
__device__ int   g_counter;                    // counts 64 epilogues (self-reset)

__device__ __forceinline__ float block_reduce(float v, float* red) {
    const int lane = threadIdx.x & 31, w = threadIdx.x >> 5;
#pragma unroll
    for (int o = 16; o; o >>= 1) v += __shfl_down_sync(0xffffffffu, v, o);
    if (lane == 0) red[w] = v;
    __syncthreads();
    if (threadIdx.x < 32) {
        v = red[threadIdx.x];
#pragma unroll
        for (int o = 16; o; o >>= 1) v += __shfl_down_sync(0xffffffffu, v, o);
        if (threadIdx.x == 0) red[0] = v;
    }
    __syncthreads();
    float r = red[0];
    __syncthreads();
    return r;
}

__global__ void __cluster_dims__(CSZ, 1, 1) __launch_bounds__(NT, 1)
fused8(const float* __restrict__ in0, const float* __restrict__ in1,
       float* __restrict__ out) {
    extern __shared__ char smem[];
    __nv_bfloat162* data  = (__nv_bfloat162*)(smem + DATA_OFF);  // [CHC][288]
    float2*         buf2  = (float2*)(smem + BUF_OFF);           // [8][288]
    float*          heatC = (float*)(smem + HEATC_OFF);
    unsigned char*  slab  = (unsigned char*)(smem + SLAB_OFF);
    float*          red   = (float*)(smem + RED_OFF);
    int*            flg   = (int*)(smem + FLG_OFF);

    cg::cluster_group cl = cg::this_cluster();
    const int cta   = blockIdx.x;
    const int chunk = cta / CSZ;                 // img*64 + b
    const int r     = cta % CSZ;                 // cluster rank
    const int b     = chunk & (NB - 1);
    const float* src = ((chunk >= NB) ? in1 : in0)
                     + ((size_t)b * NC + (size_t)r * CHC) * NN;

    const int tid  = threadIdx.x;
    const int w    = tid >> 5;                   // 0..31
    const int lane = tid & 31;

    // ---- Phase 1: stream own 96 channels ONCE: LDG f32 -> heat partials + bf16 STS
    float2 acc[9];
#pragma unroll
    for (int j = 0; j < 9; ++j) acc[j] = make_float2(0.f, 0.f);
#pragma unroll
    for (int k = 0; k < CHC / NWARP; ++k) {      // 3 channels per warp
        const int c = w + NWARP * k;
        const float2* row = (const float2*)(src + (size_t)c * NN);
        __nv_bfloat162* drow = data + c * (NN / 2);
#pragma unroll
        for (int j = 0; j < 9; ++j) {
            float2 v = row[lane + 32 * j];
            drow[lane + 32 * j] = __float22bfloat162_rn(v);
            acc[j].x += v.x;
            acc[j].y += v.y;
        }
    }
    __syncthreads();

    // ---- Deterministic tree: 32 warp-partials -> warp 0 (fixed order, no atomics)
    // batches: +[8..15], +[16..23], +[24..31], then warps 1..7 -> warp 0
    if (w >= 8 && w < 16) {
#pragma unroll
        for (int j = 0; j < 9; ++j) buf2[(w - 8) * 288 + lane + 32 * j] = acc[j];
    }
    __syncthreads();
    if (w < 8) {
#pragma unroll
        for (int j = 0; j < 9; ++j) {
            float2 t = buf2[w * 288 + lane + 32 * j];
            acc[j].x += t.x; acc[j].y += t.y;
        }
    }
    __syncthreads();
    if (w >= 16 && w < 24) {
#pragma unroll
        for (int j = 0; j < 9; ++j) buf2[(w - 16) * 288 + lane + 32 * j] = acc[j];
    }
    __syncthreads();
    if (w < 8) {
#pragma unroll
        for (int j = 0; j < 9; ++j) {
            float2 t = buf2[w * 288 + lane + 32 * j];
            acc[j].x += t.x; acc[j].y += t.y;
        }
    }
    __syncthreads();
    if (w >= 24) {
#pragma unroll
        for (int j = 0; j < 9; ++j) buf2[(w - 24) * 288 + lane + 32 * j] = acc[j];
    }
    __syncthreads();
    if (w < 8) {
#pragma unroll
        for (int j = 0; j < 9; ++j) {
            float2 t = buf2[w * 288 + lane + 32 * j];
            acc[j].x += t.x; acc[j].y += t.y;
        }
    }
    __syncthreads();
    if (w >= 1 && w < 8) {
#pragma unroll
        for (int j = 0; j < 9; ++j) buf2[(w - 1) * 288 + lane + 32 * j] = acc[j];
    }
    __syncthreads();
    if (w == 0) {
#pragma unroll
        for (int s = 0; s < 7; ++s) {
#pragma unroll
            for (int j = 0; j < 9; ++j) {
                float2 t = buf2[s * 288 + lane + 32 * j];
                acc[j].x += t.x; acc[j].y += t.y;
            }
        }
        float2* hp = (float2*)(g_heatP + ((size_t)chunk * CSZ + r) * NN);
#pragma unroll
        for (int j = 0; j < 9; ++j) hp[lane + 32 * j] = acc[j];
    }
    __threadfence();
    __syncthreads();
    cl.sync();                                   // the ONLY cluster barrier

    // ---- Combine 8 rank-partials (fixed order => deterministic, identical on all)
    for (int i = tid; i < NN; i += NT) {
        const float* hp = g_heatP + (size_t)chunk * CSZ * NN + i;
        float h = 0.f;
#pragma unroll
        for (int rr = 0; rr < CSZ; ++rr) h += hp[rr * NN];
        heatC[i] = h;
    }
    __syncthreads();

    // ---- Rank + tercile label: warp w owns n in [18w, 18w+18)
    {
        float kr[18];
#pragma unroll
        for (int j = 0; j < 18; ++j) kr[j] = heatC[lane + 32 * j];
#pragma unroll
        for (int i = 0; i < 18; ++i) {
            int n = 18 * w + i;
            float hn = heatC[n];
            unsigned cnt = 0;
#pragma unroll
            for (int j = 0; j < 18; ++j) {
                int m = lane + 32 * j;
                cnt += (kr[j] > hn) || (kr[j] == hn && m < n);
            }
            unsigned rk = __reduce_add_sync(0xffffffffu, cnt);
            if (lane == 0) slab[n] = (unsigned char)(rk / GS);
        }
    }
    __syncthreads();

    // ---- Per-lane label bitmasks (positions 2*(lane+32j), +1)
    unsigned bm0 = 0, bm1 = 0;
#pragma unroll
    for (int j = 0; j < 9; ++j) {
        int n = 2 * (lane + 32 * j);
        unsigned char l0 = slab[n], l1 = slab[n + 1];
        bm0 |= ((l0 == 0) ? 1u : 0u) << (2 * j);
        bm0 |= ((l1 == 0) ? 1u : 0u) << (2 * j + 1);
        bm1 |= ((l0 == 1) ? 1u : 0u) << (2 * j);
        bm1 |= ((l1 == 1) ? 1u : 0u) << (2 * j + 1);
    }

    // ---- Group sums from SMEM (NO second DRAM pass)
    float* dst = g_gsum + (size_t)chunk * NG * NC;
#pragma unroll
    for (int k = 0; k < CHC / NWARP; ++k) {
        const int c = w + NWARP * k;
        const __nv_bfloat162* row = data + c * (NN / 2);
        float tot = 0.f, s0 = 0.f, s1 = 0.f;
#pragma unroll
        for (int j = 0; j < 9; ++j) {
            float2 v = __bfloat1622float2(row[lane + 32 * j]);
            tot += v.x + v.y;
            if ((bm0 >> (2 * j)) & 1u)     s0 += v.x;
            if ((bm0 >> (2 * j + 1)) & 1u) s0 += v.y;
            if ((bm1 >> (2 * j)) & 1u)     s1 += v.x;
            if ((bm1 >> (2 * j + 1)) & 1u) s1 += v.y;
        }
#pragma unroll
        for (int o = 16; o; o >>= 1) {
            tot += __shfl_down_sync(0xffffffffu, tot, o);
            s0  += __shfl_down_sync(0xffffffffu, s0, o);
            s1  += __shfl_down_sync(0xffffffffu, s1, o);
        }
        if (lane == 0) {
            int cg_ = r * CHC + c;
            dst[cg_]          = s0;
            dst[NC + cg_]     = s1;
            dst[2 * NC + cg_] = tot - s0 - s1;   // 1/192 cancels in L2 norm
        }
    }
    __threadfence();
    __syncthreads();

    // ---- Pairing: 16th CTA of this b (8 ranks x 2 images) does normalize+SSD
    if (tid == 0) {
        int prev = atomicAdd(&g_done[b], 1);
        if (prev == 2 * CSZ - 1) { g_done[b] = 0; *flg = 1; }   // self-reset
        else                     { *flg = 0; }
    }
    __syncthreads();
    if (!*flg) return;
    __threadfence();

    const float* v1 = g_gsum + (size_t)b * NG * NC;
    const float* v2 = g_gsum + (size_t)(NB + b) * NG * NC;

    float ss1 = 0.f, ss2 = 0.f;
    for (int i = tid; i < NG * NC; i += NT) {
        float a = v1[i], c = v2[i];
        ss1 = fmaf(a, a, ss1);
        ss2 = fmaf(c, c, ss2);
    }
    ss1 = block_reduce(ss1, red);
    ss2 = block_reduce(ss2, red);
    float i1 = 1.f / fmaxf(sqrtf(ss1), 1e-12f);
    float i2 = 1.f / fmaxf(sqrtf(ss2), 1e-12f);

    float acc2 = 0.f;
    for (int i = tid; i < NG * NC; i += NT) {
        float d = v1[i] * i1 - v2[i] * i2;
        acc2 = fmaf(d, d, acc2);
    }
    acc2 = block_reduce(acc2, red);

    if (tid == 0) {
        g_partial[b] = acc2;
        __threadfence();
        int prev = atomicAdd(&g_counter, 1);
        if (prev == NB - 1) { g_counter = 0; *flg = 1; }
        else                { *flg = 0; }
    }
    __syncthreads();

    if (*flg && tid < 32) {
        float v = g_partial[tid] + g_partial[tid + 32];
#pragma unroll
        for (int o = 16; o; o >>= 1) v += __shfl_down_sync(0xffffffffu, v, o);
        if (tid == 0) out[0] = v * (1.f / (float)(NB * NG * NC));
    }
}

extern "C" void kernel_launch(void* const* d_in, const int* in_sizes, int n_in,
                              void* d_out, int out_size) {
    const float* in0 = (const float*)d_in[0];
    const float* in1 = (const float*)d_in[1];
    float* out = (float*)d_out;
    (void)in_sizes; (void)n_in; (void)out_size;

    cudaFuncSetAttribute(fused8, cudaFuncAttributeMaxDynamicSharedMemorySize, SMEM_TOTAL);

    fused8<<<2 * NB * CSZ, NT, SMEM_TOTAL>>>(in0, in1, out);
}

// round 12
// speedup vs baseline: 1.4584x; 1.0459x over previous
#include <cuda_runtime.h>
#include <stdint.h>

#define NB 64
#define NC 768
#define NN 576
#define NG 3
#define GS 192
#define NQ 4                 // quarters per chunk
#define QC (NC / NQ)         // 192 channels per quarter
#define NT 1024
#define NWARP 32

__device__ float g_heatP[2 * NB * NQ * NN];  // per-(chunk,quarter) heat partials
__device__ float g_gsum [2 * NB * NG * NC];  // [chunk][g][c]
__device__ float g_partial[NB];
__device__ int   g_arrive[2 * NB];           // quarter arrivals per chunk (self-reset)
__device__ int   g_depart[2 * NB];           // departures (last resets both)
__device__ int   g_done[NB];                 // 8 CTAs per b (self-reset)
__device__ int   g_counter;                  // 64 epilogues (self-reset)

__device__ __forceinline__ float block_reduce(float v, float* red) {
    const int lane = threadIdx.x & 31, w = threadIdx.x >> 5;
#pragma unroll
    for (int o = 16; o; o >>= 1) v += __shfl_down_sync(0xffffffffu, v, o);
    if (lane == 0) red[w] = v;
    __syncthreads();
    if (threadIdx.x < 32) {
        v = red[threadIdx.x];
#pragma unroll
        for (int o = 16; o; o >>= 1) v += __shfl_down_sync(0xffffffffu, v, o);
        if (threadIdx.x == 0) red[0] = v;
    }
    __syncthreads();
    float r = red[0];
    __syncthreads();
    return r;
}

// ---------------------------------------------------------------------------
// One CTA per (img,b,quarter). Stream quarter once -> heat partial -> global;
// spin for 4 partials; combine (fixed order); rank; phase 2 from L2-hot data.
// ---------------------------------------------------------------------------
__global__ __launch_bounds__(NT, 1)
void fused_q(const float* __restrict__ in0, const float* __restrict__ in1,
             float* __restrict__ out) {
    __shared__ float         heatP[NN];
    __shared__ float         heatC[NN];
    __shared__ unsigned char slab[NN];
    __shared__ float         red[NWARP];
    __shared__ int           flg;

    const int id    = blockIdx.x;              // 0..511
    const int chunk = id >> 2;                 // img*64 + b
    const int q     = id & 3;
    const int b     = chunk & (NB - 1);
    const float* src = ((chunk >= NB) ? in1 : in0)
                     + ((size_t)b * NC + (size_t)q * QC) * NN;

    const int tid  = threadIdx.x;
    const int w    = tid >> 5;                 // 0..31
    const int lane = tid & 31;

    for (int i = tid; i < NN; i += NT) heatP[i] = 0.f;
    __syncthreads();

    // ---- Phase 1: stream own 192 channels once; warp w: c = w + 32k, k<6
    float2 acc[9];
#pragma unroll
    for (int j = 0; j < 9; ++j) acc[j] = make_float2(0.f, 0.f);
#pragma unroll 2
    for (int k = 0; k < QC / NWARP; ++k) {
        const float2* row = (const float2*)(src + (size_t)(w + NWARP * k) * NN);
#pragma unroll
        for (int j = 0; j < 9; ++j) {
            float2 v = row[lane + 32 * j];
            acc[j].x += v.x;
            acc[j].y += v.y;
        }
    }
#pragma unroll
    for (int j = 0; j < 9; ++j) {
        int n = 2 * (lane + 32 * j);
        atomicAdd(&heatP[n],     acc[j].x);
        atomicAdd(&heatP[n + 1], acc[j].y);
    }
    __syncthreads();

    // ---- Publish partial heat, arrive
    {
        float* hp = g_heatP + ((size_t)chunk * NQ + q) * NN;
        for (int i = tid; i < NN; i += NT) hp[i] = heatP[i];
    }
    __threadfence();
    __syncthreads();
    if (tid == 0) {
        atomicAdd(&g_arrive[chunk], 1);
        // spin until all 4 quarters arrived (partners co-resident by launch order)
        while (*((volatile int*)&g_arrive[chunk]) < NQ) __nanosleep(64);
    }
    __syncthreads();
    __threadfence();   // acquire: partners' heat writes now visible

    // ---- Combine 4 partials in FIXED order (identical result on all 4 CTAs)
    for (int i = tid; i < NN; i += NT) {
        const float* hp = g_heatP + (size_t)chunk * NQ * NN + i;
        heatC[i] = ((hp[0] + hp[NN]) + hp[2 * NN]) + hp[3 * NN];
    }
    __syncthreads();

    // ---- Departure bookkeeping: last of 4 resets both counters for replay
    if (tid == 0) {
        __threadfence();
        int p = atomicAdd(&g_depart[chunk], 1);
        if (p == NQ - 1) { g_arrive[chunk] = 0; g_depart[chunk] = 0; }
    }

    // ---- Rank + tercile label: warp w owns n in [18w, 18w+18)
    {
        float kr[18];
#pragma unroll
        for (int j = 0; j < 18; ++j) kr[j] = heatC[lane + 32 * j];
#pragma unroll
        for (int i = 0; i < 18; ++i) {
            int n = 18 * w + i;
            float hn = heatC[n];
            unsigned cnt = 0;
#pragma unroll
            for (int j = 0; j < 18; ++j) {
                int m = lane + 32 * j;
                cnt += (kr[j] > hn) || (kr[j] == hn && m < n);
            }
            unsigned rk = __reduce_add_sync(0xffffffffu, cnt);
            if (lane == 0) slab[n] = (unsigned char)(rk / GS);
        }
    }
    __syncthreads();

    // ---- Per-lane label bitmasks
    unsigned bm0 = 0, bm1 = 0;
#pragma unroll
    for (int j = 0; j < 9; ++j) {
        int n = 2 * (lane + 32 * j);
        unsigned char l0 = slab[n], l1 = slab[n + 1];
        bm0 |= ((l0 == 0) ? 1u : 0u) << (2 * j);
        bm0 |= ((l1 == 0) ? 1u : 0u) << (2 * j + 1);
        bm1 |= ((l0 == 1) ? 1u : 0u) << (2 * j);
        bm1 |= ((l1 == 1) ? 1u : 0u) << (2 * j + 1);
    }

    // ---- Phase 2: re-read own quarter (L2-hot; live window ~65 MB < L2)
    float* dst = g_gsum + (size_t)chunk * NG * NC;
#pragma unroll
    for (int k = 0; k < QC / NWARP; ++k) {
        const int cl_ = w + NWARP * k;
        const float2* row = (const float2*)(src + (size_t)cl_ * NN);
        float tot = 0.f, s0 = 0.f, s1 = 0.f;
#pragma unroll
        for (int j = 0; j < 9; ++j) {
            float2 v = row[lane + 32 * j];
            tot += v.x + v.y;
            if ((bm0 >> (2 * j)) & 1u)     s0 += v.x;
            if ((bm0 >> (2 * j + 1)) & 1u) s0 += v.y;
            if ((bm1 >> (2 * j)) & 1u)     s1 += v.x;
            if ((bm1 >> (2 * j + 1)) & 1u) s1 += v.y;
        }
#pragma unroll
        for (int o = 16; o; o >>= 1) {
            tot += __shfl_down_sync(0xffffffffu, tot, o);
            s0  += __shfl_down_sync(0xffffffffu, s0, o);
            s1  += __shfl_down_sync(0xffffffffu, s1, o);
        }
        if (lane == 0) {
            int cg_ = q * QC + cl_;
            dst[cg_]          = s0;
            dst[NC + cg_]     = s1;
            dst[2 * NC + cg_] = tot - s0 - s1;   // 1/192 cancels in L2 norm
        }
    }
    __threadfence();
    __syncthreads();

    // ---- Pairing epilogue: 8th CTA of this b (2 img x 4 quarters) does SSD
    if (tid == 0) {
        int prev = atomicAdd(&g_done[b], 1);
        if (prev == 2 * NQ - 1) { g_done[b] = 0; flg = 1; }   // self-reset
        else                    { flg = 0; }
    }
    __syncthreads();
    if (!flg) return;
    __threadfence();

    const float* v1 = g_gsum + (size_t)b * NG * NC;
    const float* v2 = g_gsum + (size_t)(NB + b) * NG * NC;

    float ss1 = 0.f, ss2 = 0.f;
    for (int i = tid; i < NG * NC; i += NT) {
        float a = v1[i], c = v2[i];
        ss1 = fmaf(a, a, ss1);
        ss2 = fmaf(c, c, ss2);
    }
    ss1 = block_reduce(ss1, red);
    ss2 = block_reduce(ss2, red);
    float i1 = 1.f / fmaxf(sqrtf(ss1), 1e-12f);
    float i2 = 1.f / fmaxf(sqrtf(ss2), 1e-12f);

    float acc2 = 0.f;
    for (int i = tid; i < NG * NC; i += NT) {
        float d = v1[i] * i1 - v2[i] * i2;
        acc2 = fmaf(d, d, acc2);
    }
    acc2 = block_reduce(acc2, red);

    if (tid == 0) {
        g_partial[b] = acc2;
        __threadfence();
        int prev = atomicAdd(&g_counter, 1);
        if (prev == NB - 1) { g_counter = 0; flg = 1; }
        else                { flg = 0; }
    }
    __syncthreads();

    if (flg && tid < 32) {
        float v = g_partial[tid] + g_partial[tid + 32];
#pragma unroll
        for (int o = 16; o; o >>= 1) v += __shfl_down_sync(0xffffffffu, v, o);
        if (tid == 0) out[0] = v * (1.f / (float)(NB * NG * NC));
    }
}

extern "C" void kernel_launch(void* const* d_in, const int* in_sizes, int n_in,
                              void* d_out, int out_size) {
    const float* in0 = (const float*)d_in[0];
    const float* in1 = (const float*)d_in[1];
    float* out = (float*)d_out;
    (void)in_sizes; (void)n_in; (void)out_size;

    fused_q<<<2 * NB * NQ, NT>>>(in0, in1, out);
}

// round 13
// speedup vs baseline: 2.9837x; 2.0458x over previous
#include <cuda_runtime.h>
#include <stdint.h>

#define NB 64
#define NC 768
#define NN 576
#define NG 3
#define GS 192
#define HC (NC / 2)          // 384 channels per half
#define NT 512
#define NWARP 16

__device__ float g_heatP[2 * NB * 2 * NN];   // per-(chunk,half) heat partials
__device__ float g_gsum [2 * NB * NG * NC];  // [chunk][g][c]
__device__ float g_partial[NB];
__device__ int   g_arrive[2 * NB];           // half arrivals per chunk (self-reset)
__device__ int   g_depart[2 * NB];
__device__ int   g_done[NB];                 // 4 CTAs per b (self-reset)
__device__ int   g_counter;                  // 64 epilogues (self-reset)

__device__ __forceinline__ float block_reduce(float v, float* red) {
    const int lane = threadIdx.x & 31, w = threadIdx.x >> 5;
#pragma unroll
    for (int o = 16; o; o >>= 1) v += __shfl_down_sync(0xffffffffu, v, o);
    if (lane == 0) red[w] = v;
    __syncthreads();
    if (threadIdx.x < 16) {
        v = red[threadIdx.x];
#pragma unroll
        for (int o = 8; o; o >>= 1) v += __shfl_down_sync(0x0000ffffu, v, o);
        if (threadIdx.x == 0) red[0] = v;
    }
    __syncthreads();
    float r = red[0];
    __syncthreads();
    return r;
}

// ---------------------------------------------------------------------------
// One CTA per (img,b,half): 256 CTAs x 512 thr, 2/SM -> ALL resident at once.
// Phase1 own 384 ch -> partial heat -> 2-partner global handshake -> rank ->
// phase2 own 384 ch (reverse order) -> inline pairing epilogue.
// ---------------------------------------------------------------------------
__global__ __launch_bounds__(NT, 2)
void fused_h(const float* __restrict__ in0, const float* __restrict__ in1,
             float* __restrict__ out) {
    __shared__ float         heatP[NN];
    __shared__ float         heatC[NN];
    __shared__ unsigned char slab[NN];
    __shared__ float         red[NWARP];
    __shared__ int           flg;

    const int id    = blockIdx.x;              // 0..255
    const int chunk = id >> 1;                 // img*64 + b
    const int h     = id & 1;
    const int b     = chunk & (NB - 1);
    const float* src = ((chunk >= NB) ? in1 : in0)
                     + ((size_t)b * NC + (size_t)h * HC) * NN;

    const int tid  = threadIdx.x;
    const int w    = tid >> 5;                 // 0..15
    const int lane = tid & 31;

    for (int i = tid; i < NN; i += NT) heatP[i] = 0.f;
    __syncthreads();

    // ---- Phase 1: stream own 384 channels; warp w: c = w + 16k (k<24)
    float2 acc[9];
#pragma unroll
    for (int j = 0; j < 9; ++j) acc[j] = make_float2(0.f, 0.f);
#pragma unroll 2
    for (int k = 0; k < HC / NWARP; ++k) {
        const float2* row = (const float2*)(src + (size_t)(w + NWARP * k) * NN);
#pragma unroll
        for (int j = 0; j < 9; ++j) {
            float2 v = row[lane + 32 * j];
            acc[j].x += v.x;
            acc[j].y += v.y;
        }
    }
#pragma unroll
    for (int j = 0; j < 9; ++j) {
        int n = 2 * (lane + 32 * j);
        atomicAdd(&heatP[n],     acc[j].x);
        atomicAdd(&heatP[n + 1], acc[j].y);
    }
    __syncthreads();

    // ---- Publish partial heat; 2-partner handshake (all CTAs resident)
    {
        float* hp = g_heatP + ((size_t)chunk * 2 + h) * NN;
        for (int i = tid; i < NN; i += NT) hp[i] = heatP[i];
    }
    __threadfence();
    __syncthreads();
    if (tid == 0) {
        atomicAdd(&g_arrive[chunk], 1);
        while (*((volatile int*)&g_arrive[chunk]) < 2) __nanosleep(32);
    }
    __syncthreads();
    __threadfence();   // acquire partner's writes

    // ---- Combine 2 partials in fixed order (identical on both CTAs)
    for (int i = tid; i < NN; i += NT) {
        const float* hp = g_heatP + (size_t)chunk * 2 * NN + i;
        heatC[i] = hp[0] + hp[NN];
    }
    __syncthreads();

    // ---- Departure: last of 2 resets counters for graph replay
    if (tid == 0) {
        __threadfence();
        int p = atomicAdd(&g_depart[chunk], 1);
        if (p == 1) { g_arrive[chunk] = 0; g_depart[chunk] = 0; }
    }

    // ---- Rank + tercile label: warp w owns n in [36w, 36w+36)
    {
        float kr[18];
#pragma unroll
        for (int j = 0; j < 18; ++j) kr[j] = heatC[lane + 32 * j];
#pragma unroll
        for (int i = 0; i < 36; ++i) {
            int n = 36 * w + i;
            float hn = heatC[n];
            unsigned cnt = 0;
#pragma unroll
            for (int j = 0; j < 18; ++j) {
                int m = lane + 32 * j;
                cnt += (kr[j] > hn) || (kr[j] == hn && m < n);
            }
            unsigned rk = __reduce_add_sync(0xffffffffu, cnt);
            if (lane == 0) slab[n] = (unsigned char)(rk / GS);
        }
    }
    __syncthreads();

    // ---- Per-lane label bitmasks
    unsigned bm0 = 0, bm1 = 0;
#pragma unroll
    for (int j = 0; j < 9; ++j) {
        int n = 2 * (lane + 32 * j);
        unsigned char l0 = slab[n], l1 = slab[n + 1];
        bm0 |= ((l0 == 0) ? 1u : 0u) << (2 * j);
        bm0 |= ((l1 == 0) ? 1u : 0u) << (2 * j + 1);
        bm1 |= ((l0 == 1) ? 1u : 0u) << (2 * j);
        bm1 |= ((l1 == 1) ? 1u : 0u) << (2 * j + 1);
    }

    // ---- Phase 2: re-read own 384 channels in REVERSE (L2 freshest first)
    float* dst = g_gsum + (size_t)chunk * NG * NC;
    for (int k = 0; k < HC / NWARP; ++k) {
        const int cl_ = (HC - 1) - (w + NWARP * k);
        const float2* row = (const float2*)(src + (size_t)cl_ * NN);
        float tot = 0.f, s0 = 0.f, s1 = 0.f;
#pragma unroll
        for (int j = 0; j < 9; ++j) {
            float2 v = __ldcs(&row[lane + 32 * j]);
            tot += v.x + v.y;
            if ((bm0 >> (2 * j)) & 1u)     s0 += v.x;
            if ((bm0 >> (2 * j + 1)) & 1u) s0 += v.y;
            if ((bm1 >> (2 * j)) & 1u)     s1 += v.x;
            if ((bm1 >> (2 * j + 1)) & 1u) s1 += v.y;
        }
#pragma unroll
        for (int o = 16; o; o >>= 1) {
            tot += __shfl_down_sync(0xffffffffu, tot, o);
            s0  += __shfl_down_sync(0xffffffffu, s0, o);
            s1  += __shfl_down_sync(0xffffffffu, s1, o);
        }
        if (lane == 0) {
            int cg_ = h * HC + cl_;
            dst[cg_]          = s0;
            dst[NC + cg_]     = s1;
            dst[2 * NC + cg_] = tot - s0 - s1;   // 1/192 cancels in L2 norm
        }
    }
    __threadfence();
    __syncthreads();

    // ---- Pairing epilogue: 4th CTA of this b (2 img x 2 halves) does SSD
    if (tid == 0) {
        int prev = atomicAdd(&g_done[b], 1);
        if (prev == 3) { g_done[b] = 0; flg = 1; }   // self-reset
        else           { flg = 0; }
    }
    __syncthreads();
    if (!flg) return;
    __threadfence();

    const float* v1 = g_gsum + (size_t)b * NG * NC;
    const float* v2 = g_gsum + (size_t)(NB + b) * NG * NC;

    float ss1 = 0.f, ss2 = 0.f;
    for (int i = tid; i < NG * NC; i += NT) {
        float a = v1[i], c = v2[i];
        ss1 = fmaf(a, a, ss1);
        ss2 = fmaf(c, c, ss2);
    }
    ss1 = block_reduce(ss1, red);
    ss2 = block_reduce(ss2, red);
    float i1 = 1.f / fmaxf(sqrtf(ss1), 1e-12f);
    float i2 = 1.f / fmaxf(sqrtf(ss2), 1e-12f);

    float acc2 = 0.f;
    for (int i = tid; i < NG * NC; i += NT) {
        float d = v1[i] * i1 - v2[i] * i2;
        acc2 = fmaf(d, d, acc2);
    }
    acc2 = block_reduce(acc2, red);

    if (tid == 0) {
        g_partial[b] = acc2;
        __threadfence();
        int prev = atomicAdd(&g_counter, 1);
        if (prev == NB - 1) { g_counter = 0; flg = 1; }
        else                { flg = 0; }
    }
    __syncthreads();

    if (flg && tid < 32) {
        float v = g_partial[tid] + g_partial[tid + 32];
#pragma unroll
        for (int o = 16; o; o >>= 1) v += __shfl_down_sync(0xffffffffu, v, o);
        if (tid == 0) out[0] = v * (1.f / (float)(NB * NG * NC));
    }
}

extern "C" void kernel_launch(void* const* d_in, const int* in_sizes, int n_in,
                              void* d_out, int out_size) {
    const float* in0 = (const float*)d_in[0];
    const float* in1 = (const float*)d_in[1];
    float* out = (float*)d_out;
    (void)in_sizes; (void)n_in; (void)out_size;

    fused_h<<<4 * NB, NT>>>(in0, in1, out);
}

// round 14
// speedup vs baseline: 3.3953x; 1.1379x over previous
#include <cuda_runtime.h>
#include <stdint.h>

#define NB 64
#define NC 768
#define NN 576
#define NG 3
#define GS 192
#define NT 1024
#define NWP 32          // warps per CTA

__device__ float g_gsum[2 * NB * NG * NC];   // [img*NB + b][3*NC]
__device__ float g_partial[NB];
__device__ int   g_pair[NB];                 // per-b arrival flag (self-resetting)
__device__ int   g_counter;                  // final-sum counter (self-resetting)

__device__ __forceinline__ float block_reduce(float v, float* red) {
    const int lane = threadIdx.x & 31, w = threadIdx.x >> 5;
#pragma unroll
    for (int o = 16; o; o >>= 1) v += __shfl_down_sync(0xffffffffu, v, o);
    if (lane == 0) red[w] = v;
    __syncthreads();
    if (threadIdx.x < 32) {
        v = red[threadIdx.x];
#pragma unroll
        for (int o = 16; o; o >>= 1) v += __shfl_down_sync(0xffffffffu, v, o);
        if (threadIdx.x == 0) red[0] = v;
    }
    __syncthreads();
    float r = red[0];
    __syncthreads();
    return r;
}

// ---------------------------------------------------------------------------
// One CTA per (img,b), 32 warps. Phase1 (heat partials + per-channel totals)
// -> deterministic smem tree -> rank -> phase2 (masked group sums, s2 via tot)
// -> inline pairing epilogue. NO smem atomics anywhere.
// ---------------------------------------------------------------------------
__global__ __launch_bounds__(NT, 1)
void fused_kernel(const float* __restrict__ in0, const float* __restrict__ in1,
                  float* __restrict__ out) {
    __shared__ float2        hc2[NN / 2];        // heat as float2 (heat[n] scalar view)
    __shared__ float2        buf[8 * (NN / 2)];  // tree staging: 8 x 288 float2
    __shared__ float         tots[NC];           // per-channel totals
    __shared__ unsigned char slab[NN];
    __shared__ float         red[NWP];
    __shared__ int           flg;

    const int ib   = blockIdx.x;               // img*NB + b
    const int b    = ib & (NB - 1);
    const float* src = ((ib >= NB) ? in1 : in0) + (size_t)b * NC * NN;

    const int tid  = threadIdx.x;
    const int w    = tid >> 5;                 // 0..31
    const int lane = tid & 31;
    float* heatC = (float*)hc2;

    // ---- Phase 1: warp w streams channels c = w + 32k (k<24).
    // acc[j] accumulates heat partials at positions 2*(lane+32j), +1.
    // Per channel, also warp-reduce the total into tots[c].
    float2 acc[9];
#pragma unroll
    for (int j = 0; j < 9; ++j) acc[j] = make_float2(0.f, 0.f);
#pragma unroll 2
    for (int k = 0; k < NC / NWP; ++k) {
        const int c = w + NWP * k;
        const float2* row = (const float2*)(src + (size_t)c * NN);
        float2 v[9];
#pragma unroll
        for (int j = 0; j < 9; ++j) v[j] = row[lane + 32 * j];
        float t = 0.f;
#pragma unroll
        for (int j = 0; j < 9; ++j) {
            acc[j].x += v[j].x;
            acc[j].y += v[j].y;
            t += v[j].x + v[j].y;
        }
#pragma unroll
        for (int o = 16; o; o >>= 1) t += __shfl_down_sync(0xffffffffu, t, o);
        if (lane == 0) tots[c] = t;
    }
    __syncthreads();

    // ---- Deterministic tree: 32 warp partials -> warp 0 -> heatC
    const int li = lane;                        // buf slot index helper
    if (w >= 8 && w < 16) {
#pragma unroll
        for (int j = 0; j < 9; ++j) buf[(w - 8) * 288 + li + 32 * j] = acc[j];
    }
    __syncthreads();
    if (w < 8) {
#pragma unroll
        for (int j = 0; j < 9; ++j) {
            float2 t = buf[w * 288 + li + 32 * j];
            acc[j].x += t.x; acc[j].y += t.y;
        }
    }
    __syncthreads();
    if (w >= 16 && w < 24) {
#pragma unroll
        for (int j = 0; j < 9; ++j) buf[(w - 16) * 288 + li + 32 * j] = acc[j];
    }
    __syncthreads();
    if (w < 8) {
#pragma unroll
        for (int j = 0; j < 9; ++j) {
            float2 t = buf[w * 288 + li + 32 * j];
            acc[j].x += t.x; acc[j].y += t.y;
        }
    }
    __syncthreads();
    if (w >= 24) {
#pragma unroll
        for (int j = 0; j < 9; ++j) buf[(w - 24) * 288 + li + 32 * j] = acc[j];
    }
    __syncthreads();
    if (w < 8) {
#pragma unroll
        for (int j = 0; j < 9; ++j) {
            float2 t = buf[w * 288 + li + 32 * j];
            acc[j].x += t.x; acc[j].y += t.y;
        }
    }
    __syncthreads();
    if (w >= 1 && w < 8) {
#pragma unroll
        for (int j = 0; j < 9; ++j) buf[(w - 1) * 288 + li + 32 * j] = acc[j];
    }
    __syncthreads();
    if (w == 0) {
#pragma unroll
        for (int s = 0; s < 7; ++s) {
#pragma unroll
            for (int j = 0; j < 9; ++j) {
                float2 t = buf[s * 288 + li + 32 * j];
                acc[j].x += t.x; acc[j].y += t.y;
            }
        }
#pragma unroll
        for (int j = 0; j < 9; ++j) hc2[li + 32 * j] = acc[j];
    }
    __syncthreads();

    // ---- Rank + tercile label: warp w owns n in [18w, 18w+18)
    {
        float kr[18];
#pragma unroll
        for (int j = 0; j < 18; ++j) kr[j] = heatC[lane + 32 * j];
#pragma unroll
        for (int i = 0; i < 18; ++i) {
            int n = 18 * w + i;
            float hn = heatC[n];
            unsigned cnt = 0;
#pragma unroll
            for (int j = 0; j < 18; ++j) {
                int m = lane + 32 * j;
                cnt += (kr[j] > hn) || (kr[j] == hn && m < n);
            }
            unsigned rk = __reduce_add_sync(0xffffffffu, cnt);
            if (lane == 0) slab[n] = (unsigned char)(rk / GS);
        }
    }
    __syncthreads();

    // ---- Per-lane label bitmasks (positions 2*(lane+32j), +1)
    unsigned bm0 = 0, bm1 = 0;
#pragma unroll
    for (int j = 0; j < 9; ++j) {
        int n = 2 * (lane + 32 * j);
        unsigned char l0 = slab[n], l1 = slab[n + 1];
        bm0 |= ((l0 == 0) ? 1u : 0u) << (2 * j);
        bm0 |= ((l1 == 0) ? 1u : 0u) << (2 * j + 1);
        bm1 |= ((l0 == 1) ? 1u : 0u) << (2 * j);
        bm1 |= ((l1 == 1) ? 1u : 0u) << (2 * j + 1);
    }

    // ---- Phase 2: reverse channel order; s2 = tots[c] - s0 - s1
    float* dst = g_gsum + (size_t)ib * NG * NC;
    for (int k = 0; k < NC / NWP; ++k) {
        const int c = (NC - 1) - (w + NWP * k);
        const float2* row = (const float2*)(src + (size_t)c * NN);
        float s0 = 0.f, s1 = 0.f;
#pragma unroll
        for (int j = 0; j < 9; ++j) {
            float2 v = __ldcs(&row[lane + 32 * j]);
            if ((bm0 >> (2 * j)) & 1u)     s0 += v.x;
            if ((bm0 >> (2 * j + 1)) & 1u) s0 += v.y;
            if ((bm1 >> (2 * j)) & 1u)     s1 += v.x;
            if ((bm1 >> (2 * j + 1)) & 1u) s1 += v.y;
        }
#pragma unroll
        for (int o = 16; o; o >>= 1) {
            s0 += __shfl_down_sync(0xffffffffu, s0, o);
            s1 += __shfl_down_sync(0xffffffffu, s1, o);
        }
        if (lane == 0) {
            dst[c]          = s0;
            dst[NC + c]     = s1;
            dst[2 * NC + c] = tots[c] - s0 - s1;   // 1/192 cancels in L2 norm
        }
    }
    __syncthreads();

    // ---- Pairing: second CTA of this b computes normalize + SSD
    if (tid == 0) {
        __threadfence();
        int prev = atomicAdd(&g_pair[b], 1);
        if (prev == 1) { g_pair[b] = 0; flg = 1; }   // self-reset for replay
        else           { flg = 0; }
    }
    __syncthreads();
    if (!flg) return;
    __threadfence();

    const float* v1 = g_gsum + (size_t)b * NG * NC;          // image 1
    const float* v2 = g_gsum + (size_t)(NB + b) * NG * NC;   // image 2

    float ss1 = 0.f, ss2 = 0.f;
    for (int i = tid; i < NG * NC; i += NT) {
        float a = v1[i], c = v2[i];
        ss1 = fmaf(a, a, ss1);
        ss2 = fmaf(c, c, ss2);
    }
    ss1 = block_reduce(ss1, red);
    ss2 = block_reduce(ss2, red);
    float i1 = 1.f / fmaxf(sqrtf(ss1), 1e-12f);
    float i2 = 1.f / fmaxf(sqrtf(ss2), 1e-12f);

    float acc2 = 0.f;
    for (int i = tid; i < NG * NC; i += NT) {
        float d = v1[i] * i1 - v2[i] * i2;
        acc2 = fmaf(d, d, acc2);
    }
    acc2 = block_reduce(acc2, red);

    if (tid == 0) {
        g_partial[b] = acc2;
        __threadfence();
        int prev = atomicAdd(&g_counter, 1);
        if (prev == NB - 1) { g_counter = 0; flg = 1; }
        else                { flg = 0; }
    }
    __syncthreads();

    if (flg && tid < 32) {
        float v = g_partial[tid] + g_partial[tid + 32];
#pragma unroll
        for (int o = 16; o; o >>= 1) v += __shfl_down_sync(0xffffffffu, v, o);
        if (tid == 0) out[0] = v * (1.f / (float)(NB * NG * NC));
    }
}

extern "C" void kernel_launch(void* const* d_in, const int* in_sizes, int n_in,
                              void* d_out, int out_size) {
    const float* in0 = (const float*)d_in[0];
    const float* in1 = (const float*)d_in[1];
    float* out = (float*)d_out;
    (void)in_sizes; (void)n_in; (void)out_size;

    fused_kernel<<<2 * NB, NT>>>(in0, in1, out);
}